// round 7
// baseline (speedup 1.0000x reference)
#include <cuda_runtime.h>
#include <math.h>

#define NMODES 64
#define LSEQ   262144
#define SEG    64
#define NSEGS  (LSEQ/SEG)        /* 4096 */
#define CPT    16                /* segments composed per scan thread */
#define SCAN_T (NSEGS/CPT)       /* 256 */
#define TILE   256
#define NBLK   (LSEQ/TILE)       /* 1024 */
#define THR    128

typedef unsigned long long u64t;

// ---------------- f32x2 packed helpers (FFMA2 path, PTX-only) ----------------
__device__ __forceinline__ u64t pk2(float lo, float hi) {
    u64t r; asm("mov.b64 %0,{%1,%2};" : "=l"(r) : "f"(lo), "f"(hi)); return r;
}
__device__ __forceinline__ void upk2(float& lo, float& hi, u64t v) {
    asm("mov.b64 {%0,%1},%2;" : "=f"(lo), "=f"(hi) : "l"(v));
}
#define FMA2(d,a,b,c) asm("fma.rn.f32x2 %0,%1,%2,%3;" : "=l"(d) : "l"(a), "l"(b), "l"(c))
#define MUL2(d,a,b)   asm("mul.rn.f32x2 %0,%1,%2;"    : "=l"(d) : "l"(a), "l"(b))
#define ADD2(d,a,b)   asm("add.rn.f32x2 %0,%1,%2;"    : "=l"(d) : "l"(a), "l"(b))

// ---------------- scratch (static device globals; no allocation) ----------------
__device__ float4 g_P4[NMODES * NSEGS / 2];      // per-segment partials [n][seg]
__device__ float4 g_carry4[NMODES * NSEGS / 2];  // carry-in per segment [n][seg]
__device__ float2 g_z[NMODES];                   // z_n = exp(dt*A_n)
__device__ float2 g_cf[NMODES];                  // C_n * (z_n - 1) / A_n
__device__ float2 g_a64f[NMODES];                // z^64
__device__ float2 g_mkf[NMODES * 8];             // z^(1024 * 2^k), k=0..7

// ---------------- fast z^e: double phase reduction + MUFU sin/cos ----------------
static __device__ __forceinline__ float2 cexp_pow(double dr, double di, double e) {
    float m = expf((float)(e * dr));
    double t = e * di;
    double q = rint(t * 0.15915494309189533576888376337251);   // 1/(2*pi)
    double r = fma(q, -6.283185307179586476925286766559, t);   // t mod 2*pi
    float s, c;
    sincosf((float)r, &s, &c);
    return make_float2(m * c, m * s);
}

// ---------------- K0: per-mode constants ----------------
__global__ void k0_setup(const float* __restrict__ A_re,
                         const float* __restrict__ A_im,
                         const float* __restrict__ C,
                         const float* __restrict__ log_step) {
    int n = threadIdx.x;
    if (n >= NMODES) return;
    double dt = exp((double)log_step[0]);
    double ar = (double)A_re[n], ai = (double)A_im[n];
    double dr = dt * ar, di = dt * ai;

    float2 z = cexp_pow(dr, di, 1.0);
    g_z[n] = z;

    // coeff = Ct * (z - 1) / A
    double ctr = (double)C[2 * n], cti = (double)C[2 * n + 1];
    double wr = (double)z.x - 1.0, wi = (double)z.y;
    double den = ar * ar + ai * ai;
    double qr = (wr * ar + wi * ai) / den;
    double qi = (wi * ar - wr * ai) / den;
    g_cf[n] = make_float2((float)(ctr * qr - cti * qi),
                          (float)(ctr * qi + cti * qr));

    g_a64f[n] = cexp_pow(dr, di, 64.0);
    double e = 1024.0;
#pragma unroll
    for (int k = 0; k < 8; k++) {
        g_mkf[n * 8 + k] = cexp_pow(dr, di, e);
        e *= 2.0;
    }
}

// ---------------- K1: per-segment partials, 2 modes/thread via f32x2 ----------------
// grid = 1024 blocks x 128 threads. Block covers 256 samples (4 segs).
// q = t&31 (mode pair q,q+32), s = t>>5 (seg 0..3, one per warp).
__global__ void k1_partials(const float* __restrict__ u) {
    __shared__ u64t   su2[TILE];     // pre-duplicated {u,u}
    __shared__ float2 sp[4][64];     // [seg][mode] partials for transpose-out
    int t = threadIdx.x, tile = blockIdx.x;
    float2 f2 = ((const float2*)u)[tile * (TILE / 2) + t];
    su2[2 * t]     = pk2(f2.x, f2.x);
    su2[2 * t + 1] = pk2(f2.y, f2.y);
    int q = t & 31, s = t >> 5;

    float2 za = g_z[q], zb = g_z[q + 32];
    u64t zr = pk2(za.x, zb.x), zi = pk2(za.y, zb.y), nzi = pk2(-za.y, -zb.y);
    __syncthreads();

    u64t Pr = 0, Pi = 0;             // {0.f,0.f}
    const ulonglong2* up = (const ulonglong2*)(su2 + s * SEG);
#pragma unroll
    for (int j2 = 0; j2 < SEG / 2; j2++) {
        ulonglong2 uu = up[j2];
        u64t t0, v0;
        FMA2(t0, nzi, Pi, uu.x); MUL2(v0, zi, Pr);
        FMA2(Pr, zr, Pr, t0);    FMA2(Pi, zr, Pi, v0);
        FMA2(t0, nzi, Pi, uu.y); MUL2(v0, zi, Pr);
        FMA2(Pr, zr, Pr, t0);    FMA2(Pi, zr, Pi, v0);
    }

    float ra, rb, ia, ib;
    upk2(ra, rb, Pr); upk2(ia, ib, Pi);
    sp[s][q]      = make_float2(ra, ia);
    sp[s][q + 32] = make_float2(rb, ib);
    __syncthreads();

    // coalesced transpose-out: thread n writes its 4 segs as 2x float4
    if (t < 64) {
        float2 a = sp[0][t], b = sp[1][t], c = sp[2][t], d = sp[3][t];
        float4* dst = (float4*)((float2*)g_P4 + t * NSEGS + tile * 4);
        dst[0] = make_float4(a.x, a.y, b.x, b.y);
        dst[1] = make_float4(c.x, c.y, d.x, d.y);
    }
}

// ---------------- K2: fp32 Kogge-Stone scan, emit carries ----------------
// grid = NMODES blocks x SCAN_T(=256) threads.
__global__ void k2_scan() {
    __shared__ float2 sB[SCAN_T];
    int n = blockIdx.x, i = threadIdx.x;
    float2 a = g_a64f[n];

    float2 P[CPT];
    const float4* pp = g_P4 + (n * NSEGS) / 2 + i * (CPT / 2);
#pragma unroll
    for (int j = 0; j < CPT / 2; j++) {
        float4 v = pp[j];
        P[2 * j]     = make_float2(v.x, v.y);
        P[2 * j + 1] = make_float2(v.z, v.w);
    }

    float Br = 0.f, Bi = 0.f;
#pragma unroll
    for (int j = 0; j < CPT; j++) {
        float tr = fmaf(-a.y, Bi, P[j].x);
        float ti = fmaf( a.y, Br, P[j].y);
        Br = fmaf(a.x, Br, tr);
        Bi = fmaf(a.x, Bi, ti);
    }
    sB[i] = make_float2(Br, Bi);

#pragma unroll
    for (int k = 0; k < 8; k++) {
        int off = 1 << k;
        float2 m = g_mkf[n * 8 + k];
        __syncthreads();
        float lr = 0.f, li = 0.f;
        if (i >= off) { float2 tt = sB[i - off]; lr = tt.x; li = tt.y; }
        __syncthreads();
        if (i >= off) {
            float nr = fmaf(m.x, lr, fmaf(-m.y, li, Br));
            float ni = fmaf(m.x, li, fmaf( m.y, lr, Bi));
            Br = nr; Bi = ni;
            sB[i] = make_float2(Br, Bi);
        }
    }
    __syncthreads();

    float Er = 0.f, Ei = 0.f;
    if (i > 0) { float2 tt = sB[i - 1]; Er = tt.x; Ei = tt.y; }
    float4* cp = g_carry4 + (n * NSEGS) / 2 + i * (CPT / 2);
#pragma unroll
    for (int j = 0; j < CPT / 2; j++) {
        float4 o;
        o.x = Er; o.y = Ei;
        {
            float tr = fmaf(-a.y, Ei, P[2 * j].x);
            float ti = fmaf( a.y, Er, P[2 * j].y);
            Er = fmaf(a.x, Er, tr); Ei = fmaf(a.x, Ei, ti);
        }
        o.z = Er; o.w = Ei;
        {
            float tr = fmaf(-a.y, Ei, P[2 * j + 1].x);
            float ti = fmaf( a.y, Er, P[2 * j + 1].y);
            Er = fmaf(a.x, Er, tr); Ei = fmaf(a.x, Ei, ti);
        }
        cp[j] = o;
    }
}

// ---------------- K3: replay + output, 2 modes/thread ----------------
// grid = 1024 blocks x 128 threads. Block covers 256 samples (4 segs).
// q = t&31 (mode pair), s = t>>5 (seg, one per warp). ctb: 32 float rows.
__global__ void k3_apply(const float* __restrict__ u,
                         const float* __restrict__ D,
                         float* __restrict__ y) {
    __shared__ u64t  su2[TILE];
    __shared__ float ctb[32][TILE + 1];
    int t = threadIdx.x, tile = blockIdx.x;
    float2 f2 = ((const float2*)u)[tile * (TILE / 2) + t];
    su2[2 * t]     = pk2(f2.x, f2.x);
    su2[2 * t + 1] = pk2(f2.y, f2.y);
    int q = t & 31, s = t >> 5;
    int seg = tile * 4 + s;

    float2 za = g_z[q],  zb = g_z[q + 32];
    u64t zr = pk2(za.x, zb.x), zi = pk2(za.y, zb.y), nzi = pk2(-za.y, -zb.y);
    float2 ca = g_cf[q], cb = g_cf[q + 32];
    u64t cr = pk2(ca.x, cb.x), nci = pk2(-ca.y, -cb.y);

    const float2* gc = (const float2*)g_carry4;
    float2 xa = gc[q * NSEGS + seg], xb = gc[(q + 32) * NSEGS + seg];
    u64t Pr = pk2(xa.x, xb.x), Pi = pk2(xa.y, xb.y);
    __syncthreads();

    const ulonglong2* up = (const ulonglong2*)(su2 + s * SEG);
    float* crow = &ctb[q][s * SEG];
#pragma unroll
    for (int j2 = 0; j2 < SEG / 2; j2++) {
        ulonglong2 uu = up[j2];
        u64t t0, v0, c0;
        float lo, hi;
        FMA2(t0, nzi, Pi, uu.x); MUL2(v0, zi, Pr);
        FMA2(Pr, zr, Pr, t0);    FMA2(Pi, zr, Pi, v0);
        MUL2(c0, nci, Pi);       FMA2(c0, cr, Pr, c0);
        upk2(lo, hi, c0);
        crow[2 * j2] = lo + hi;
        FMA2(t0, nzi, Pi, uu.y); MUL2(v0, zi, Pr);
        FMA2(Pr, zr, Pr, t0);    FMA2(Pi, zr, Pi, v0);
        MUL2(c0, nci, Pi);       FMA2(c0, cr, Pr, c0);
        upk2(lo, hi, c0);
        crow[2 * j2 + 1] = lo + hi;
    }
    __syncthreads();

    float Dv = D[0];
#pragma unroll
    for (int k = 0; k < 2; k++) {
        int col = t + k * THR;
        float a0 = 0.f, a1 = 0.f, a2 = 0.f, a3 = 0.f;
#pragma unroll
        for (int r = 0; r < 32; r += 4) {
            a0 += ctb[r + 0][col];
            a1 += ctb[r + 1][col];
            a2 += ctb[r + 2][col];
            a3 += ctb[r + 3][col];
        }
        float ulo, uhi; upk2(ulo, uhi, su2[col]);
        y[tile * TILE + col] = fmaf(Dv, ulo, (a0 + a1) + (a2 + a3));
    }
}

// ---------------- host ----------------
extern "C" void kernel_launch(void* const* d_in, const int* in_sizes, int n_in,
                              void* d_out, int out_size) {
    const float* u = 0; const float* A_re = 0; const float* A_im = 0;
    const float* C = 0; const float* D = 0; const float* log_step = 0;
    for (int i = 0; i < n_in; i++) {
        int sz = in_sizes[i];
        const float* p = (const float*)d_in[i];
        if (sz == LSEQ)            { if (!u) u = p; }
        else if (sz == 2 * NMODES) { if (!C) C = p; }
        else if (sz == NMODES)     { if (!A_re) A_re = p; else A_im = p; }
        else if (sz == 1)          { if (!D) D = p; else log_step = p; }
    }
    float* y = (float*)d_out;

    k0_setup<<<1, NMODES>>>(A_re, A_im, C, log_step);
    k1_partials<<<NBLK, THR>>>(u);
    k2_scan<<<NMODES, SCAN_T>>>();
    k3_apply<<<NBLK, THR>>>(u, D, y);
}

// round 8
// speedup vs baseline: 1.4181x; 1.4181x over previous
#include <cuda_runtime.h>
#include <math.h>

#define NMODES 64
#define LSEQ   262144
#define SEG    32
#define NSEGS  (LSEQ/SEG)        /* 8192 */
#define CPT    16                /* segments composed per scan thread */
#define SCAN_T 512               /* NSEGS/CPT */
#define LEVELS 9                 /* log2(SCAN_T) */

#define K1_THR  512
#define K1_SEGS 8                /* segs per block */
#define K1_TILE (K1_SEGS*SEG)    /* 256 samples */
#define K1_BLK  (NSEGS/K1_SEGS)  /* 1024 */

#define K3_THR  128
#define K3_SEGS 8
#define K3_TILE (K3_SEGS*SEG)    /* 256 samples */
#define K3_BLK  (NSEGS/K3_SEGS)  /* 1024 */

// ---------------- scratch (static device globals; no allocation) ----------------
__device__ float2 g_P[NMODES * NSEGS];       // per-segment partials [n][seg]
__device__ float2 g_carry[NMODES * NSEGS];   // carry-in per segment [n][seg]
__device__ float2 g_z[NMODES];               // z_n = exp(dt*A_n)
__device__ float2 g_cf[NMODES];              // C_n * (z_n - 1) / A_n
__device__ float2 g_a32[NMODES];             // z^SEG
__device__ float2 g_mkf[NMODES * LEVELS];    // z^(512 * 2^k), k=0..8

// ---------------- fast z^e: double phase reduction + MUFU sin/cos ----------------
static __device__ __forceinline__ float2 cexp_pow(double dr, double di, double e) {
    float m = expf((float)(e * dr));
    double t = e * di;
    double q = rint(t * 0.15915494309189533576888376337251);   // 1/(2*pi)
    double r = fma(q, -6.283185307179586476925286766559, t);   // t mod 2*pi
    float s, c;
    sincosf((float)r, &s, &c);
    return make_float2(m * c, m * s);
}

// ---------------- K0: per-mode constants ----------------
__global__ void k0_setup(const float* __restrict__ A_re,
                         const float* __restrict__ A_im,
                         const float* __restrict__ C,
                         const float* __restrict__ log_step) {
    int n = threadIdx.x;
    if (n >= NMODES) return;
    double dt = exp((double)log_step[0]);
    double ar = (double)A_re[n], ai = (double)A_im[n];
    double dr = dt * ar, di = dt * ai;

    float2 z = cexp_pow(dr, di, 1.0);
    g_z[n] = z;

    // coeff = Ct * (z - 1) / A
    double ctr = (double)C[2 * n], cti = (double)C[2 * n + 1];
    double wr = (double)z.x - 1.0, wi = (double)z.y;
    double den = ar * ar + ai * ai;
    double qr = (wr * ar + wi * ai) / den;
    double qi = (wi * ar - wr * ai) / den;
    g_cf[n] = make_float2((float)(ctr * qr - cti * qi),
                          (float)(ctr * qi + cti * qr));

    g_a32[n] = cexp_pow(dr, di, (double)SEG);
    double e = (double)(CPT * SEG);            // 512
#pragma unroll
    for (int k = 0; k < LEVELS; k++) {
        g_mkf[n * LEVELS + k] = cexp_pow(dr, di, e);
        e *= 2.0;
    }
}

// ---------------- K1: per-segment partials, 1 mode/thread scalar ----------------
// grid = 1024 blocks x 512 threads. Block covers 256 samples (8 segs x 64 modes).
__global__ void __launch_bounds__(K1_THR) k1_partials(const float* __restrict__ u) {
    __shared__ float  su[K1_TILE];
    __shared__ float2 sp[K1_SEGS][NMODES];
    int t = threadIdx.x, tile = blockIdx.x;
    if (t < K1_TILE / 4)
        ((float4*)su)[t] = ((const float4*)u)[tile * (K1_TILE / 4) + t];
    int n = t & 63, s = t >> 6;
    float2 z = g_z[n];
    __syncthreads();

    float xr = 0.f, xi = 0.f;
    const float* up = su + s * SEG;
#pragma unroll
    for (int j = 0; j < SEG; j++) {
        float uv  = up[j];
        float tmp = fmaf(-z.y, xi, uv);
        float v   = z.y * xr;
        xr = fmaf(z.x, xr, tmp);
        xi = fmaf(z.x, xi, v);
    }
    sp[s][n] = make_float2(xr, xi);
    __syncthreads();

    // coalesced transpose-out: thread n writes its 8 segs as 4x float4
    if (t < NMODES) {
        float4* dst = (float4*)(g_P + t * NSEGS + tile * K1_SEGS);
#pragma unroll
        for (int k = 0; k < 4; k++) {
            float2 a = sp[2 * k][t], b = sp[2 * k + 1][t];
            dst[k] = make_float4(a.x, a.y, b.x, b.y);
        }
    }
}

// ---------------- K2: fp32 Kogge-Stone scan over 8192 segments, emit carries ----------------
// grid = NMODES blocks x SCAN_T(=512) threads.
__global__ void __launch_bounds__(SCAN_T) k2_scan() {
    __shared__ float2 sB[SCAN_T];
    int n = blockIdx.x, i = threadIdx.x;
    float2 a = g_a32[n];

    float2 P[CPT];
    const float4* pp = (const float4*)(g_P + n * NSEGS + i * CPT);
#pragma unroll
    for (int j = 0; j < CPT / 2; j++) {
        float4 v = pp[j];
        P[2 * j]     = make_float2(v.x, v.y);
        P[2 * j + 1] = make_float2(v.z, v.w);
    }

    float Br = 0.f, Bi = 0.f;
#pragma unroll
    for (int j = 0; j < CPT; j++) {
        float tr = fmaf(-a.y, Bi, P[j].x);
        float ti = fmaf( a.y, Br, P[j].y);
        Br = fmaf(a.x, Br, tr);
        Bi = fmaf(a.x, Bi, ti);
    }
    sB[i] = make_float2(Br, Bi);

#pragma unroll
    for (int k = 0; k < LEVELS; k++) {
        int off = 1 << k;
        float2 m = g_mkf[n * LEVELS + k];
        __syncthreads();
        float lr = 0.f, li = 0.f;
        if (i >= off) { float2 tt = sB[i - off]; lr = tt.x; li = tt.y; }
        __syncthreads();
        if (i >= off) {
            float nr = fmaf(m.x, lr, fmaf(-m.y, li, Br));
            float ni = fmaf(m.x, li, fmaf( m.y, lr, Bi));
            Br = nr; Bi = ni;
            sB[i] = make_float2(Br, Bi);
        }
    }
    __syncthreads();

    float Er = 0.f, Ei = 0.f;
    if (i > 0) { float2 tt = sB[i - 1]; Er = tt.x; Ei = tt.y; }
    float4* cp = (float4*)(g_carry + n * NSEGS + i * CPT);
#pragma unroll
    for (int j = 0; j < CPT / 2; j++) {
        float4 o;
        o.x = Er; o.y = Ei;
        {
            float tr = fmaf(-a.y, Ei, P[2 * j].x);
            float ti = fmaf( a.y, Er, P[2 * j].y);
            Er = fmaf(a.x, Er, tr); Ei = fmaf(a.x, Ei, ti);
        }
        o.z = Er; o.w = Ei;
        {
            float tr = fmaf(-a.y, Ei, P[2 * j + 1].x);
            float ti = fmaf( a.y, Er, P[2 * j + 1].y);
            Er = fmaf(a.x, Er, tr); Ei = fmaf(a.x, Ei, ti);
        }
        cp[j] = o;
    }
}

// ---------------- K3: replay + output, 4 modes/thread scalar ----------------
// grid = 1024 blocks x 128 threads. Block covers 256 samples (8 segs).
// q = t&15 (modes q, q+16, q+32, q+48), s = t>>4 (seg 0..7). ctb: 16 float rows.
__global__ void __launch_bounds__(K3_THR) k3_apply(const float* __restrict__ u,
                                                   const float* __restrict__ D,
                                                   float* __restrict__ y) {
    __shared__ float su[K3_TILE];
    __shared__ float ctb[16][K3_TILE + 1];
    int t = threadIdx.x, tile = blockIdx.x;
    ((float2*)su)[t] = ((const float2*)u)[tile * (K3_TILE / 2) + t];
    int q = t & 15, s = t >> 4;
    int seg = tile * K3_SEGS + s;

    float2 z0 = g_z[q],       z1 = g_z[q + 16];
    float2 z2 = g_z[q + 32],  z3 = g_z[q + 48];
    float2 c0 = g_cf[q],      c1 = g_cf[q + 16];
    float2 c2 = g_cf[q + 32], c3 = g_cf[q + 48];
    float2 x0 = g_carry[q * NSEGS + seg];
    float2 x1 = g_carry[(q + 16) * NSEGS + seg];
    float2 x2 = g_carry[(q + 32) * NSEGS + seg];
    float2 x3 = g_carry[(q + 48) * NSEGS + seg];
    __syncthreads();

    const float4* up   = (const float4*)(su + s * SEG);
    float*        crow = &ctb[q][s * SEG];

#define STEP(uv, idx)                                                     \
    do {                                                                  \
        float t0 = fmaf(-z0.y, x0.y, (uv)); float v0 = z0.y * x0.x;       \
        x0.x = fmaf(z0.x, x0.x, t0);        x0.y = fmaf(z0.x, x0.y, v0);  \
        float t1 = fmaf(-z1.y, x1.y, (uv)); float v1 = z1.y * x1.x;       \
        x1.x = fmaf(z1.x, x1.x, t1);        x1.y = fmaf(z1.x, x1.y, v1);  \
        float t2 = fmaf(-z2.y, x2.y, (uv)); float v2 = z2.y * x2.x;       \
        x2.x = fmaf(z2.x, x2.x, t2);        x2.y = fmaf(z2.x, x2.y, v2);  \
        float t3 = fmaf(-z3.y, x3.y, (uv)); float v3 = z3.y * x3.x;       \
        x3.x = fmaf(z3.x, x3.x, t3);        x3.y = fmaf(z3.x, x3.y, v3);  \
        float acc = c0.x * x0.x;                                          \
        acc = fmaf(-c0.y, x0.y, acc);                                     \
        acc = fmaf( c1.x, x1.x, acc); acc = fmaf(-c1.y, x1.y, acc);       \
        acc = fmaf( c2.x, x2.x, acc); acc = fmaf(-c2.y, x2.y, acc);       \
        acc = fmaf( c3.x, x3.x, acc); acc = fmaf(-c3.y, x3.y, acc);       \
        crow[idx] = acc;                                                  \
    } while (0)

#pragma unroll
    for (int j4 = 0; j4 < SEG / 4; j4++) {
        float4 uu = up[j4];
        STEP(uu.x, 4 * j4 + 0);
        STEP(uu.y, 4 * j4 + 1);
        STEP(uu.z, 4 * j4 + 2);
        STEP(uu.w, 4 * j4 + 3);
    }
#undef STEP
    __syncthreads();

    float Dv = D[0];
#pragma unroll
    for (int k = 0; k < K3_TILE / K3_THR; k++) {
        int col = t + k * K3_THR;
        float a0 = 0.f, a1 = 0.f, a2 = 0.f, a3 = 0.f;
#pragma unroll
        for (int r = 0; r < 16; r += 4) {
            a0 += ctb[r + 0][col];
            a1 += ctb[r + 1][col];
            a2 += ctb[r + 2][col];
            a3 += ctb[r + 3][col];
        }
        y[tile * K3_TILE + col] = fmaf(Dv, su[col], (a0 + a1) + (a2 + a3));
    }
}

// ---------------- host ----------------
extern "C" void kernel_launch(void* const* d_in, const int* in_sizes, int n_in,
                              void* d_out, int out_size) {
    const float* u = 0; const float* A_re = 0; const float* A_im = 0;
    const float* C = 0; const float* D = 0; const float* log_step = 0;
    for (int i = 0; i < n_in; i++) {
        int sz = in_sizes[i];
        const float* p = (const float*)d_in[i];
        if (sz == LSEQ)            { if (!u) u = p; }
        else if (sz == 2 * NMODES) { if (!C) C = p; }
        else if (sz == NMODES)     { if (!A_re) A_re = p; else A_im = p; }
        else if (sz == 1)          { if (!D) D = p; else log_step = p; }
    }
    float* y = (float*)d_out;

    k0_setup<<<1, NMODES>>>(A_re, A_im, C, log_step);
    k1_partials<<<K1_BLK, K1_THR>>>(u);
    k2_scan<<<NMODES, SCAN_T>>>();
    k3_apply<<<K3_BLK, K3_THR>>>(u, D, y);
}